// round 16
// baseline (speedup 1.0000x reference)
#include <cuda_runtime.h>
#include <math.h>

#define M      768
#define G      24             // groups of 32 boxes
#define NTP    300            // G*(G+1)/2 unordered group-pairs
#define JSPLIT 8              // j-slices of 4 boxes
#define NCHUNK (NTP * JSPLIT) // 2400 chunks = 2400 warps
#define WPB    20
#define TPB    (WPB * 32)     // 640
#define NBLK   (NCHUNK / WPB) // 120 blocks -> exactly one wave
#define QCAP   128            // worst case 4 j-iters * 32 lanes

__device__ float g_partial[NBLK][2];
__device__ int   g_count;     // zero-init; re-armed by finalize

// sqrt(d2) via MUFU rsqrt.approx (short chain, ~1e-7 rel err)
__device__ __forceinline__ float fast_sqrt(float d2)
{
    float r;
    asm("rsqrt.approx.f32 %0, %1;" : "=f"(r) : "f"(fmaxf(d2, 1e-30f)));
    return d2 * r;
}

// Clip directed edge (global g0->g1; same edge in clipping box's local frame
// l0->l1) against |x|<=hw,|y|<=hh. Returns cross(pa,pb) of surviving segment
// in the GLOBAL frame; 0 if edge misses box.
__device__ __forceinline__ float clip_contrib(
    float g0x, float g0y, float g1x, float g1y,
    float l0x, float l0y, float l1x, float l1y,
    float hw, float hh)
{
    float tlo = 0.f, thi = 1.f;
    bool empty = false;
#define CLIP_PLANE(D0, D1)                              \
    {                                                   \
        float d0 = (D0), d1 = (D1);                     \
        bool o0 = d0 < 0.f, o1 = d1 < 0.f;              \
        empty = empty || (o0 && o1);                    \
        float t = __fdividef(d0, d0 - d1);              \
        if (o0) tlo = fmaxf(tlo, t);                    \
        if (o1) thi = fminf(thi, t);                    \
    }
    CLIP_PLANE(hw - l0x, hw - l1x)
    CLIP_PLANE(hw + l0x, hw + l1x)
    CLIP_PLANE(hh - l0y, hh - l1y)
    CLIP_PLANE(hh + l0y, hh + l1y)
#undef CLIP_PLANE
    if (empty || tlo >= thi) return 0.f;
    float ex = g1x - g0x, ey = g1y - g0y;
    float ax = g0x + tlo * ex, ay = g0y + tlo * ey;
    float bx = g0x + thi * ex, by = g0y + thi * ey;
    return ax * by - ay * bx;
}

// Exact rotated-rect IoU hinge for pair (i,j); vectorized float2 loads.
__device__ __forceinline__ float iou_hinge(const float* __restrict__ pred,
                                           int i, int j)
{
    const float2* pa = (const float2*)(pred + i * 6);   // 8B-aligned (24B rows)
    const float2* pb = (const float2*)(pred + j * 6);
    float2 a0 = __ldg(pa), a1 = __ldg(pa + 1), a2 = __ldg(pa + 2);
    float2 b0 = __ldg(pb), b1 = __ldg(pb + 1), b2 = __ldg(pb + 2);
    float acx = a0.x, acy = a0.y, aw = a1.x, ah = a1.y, ac = a2.x, as = a2.y;
    float bcx = b0.x, bcy = b0.y, bw = b1.x, bh = b1.y, bc = b2.x, bs = b2.y;

    float haw = 0.5f * aw, hah = 0.5f * ah;
    float hbw = 0.5f * bw, hbh = 0.5f * bh;

    float gxA[4], gyA[4], gxB[4], gyB[4];
    float lxA[4], lyA[4], lxB[4], lyB[4];
    const float SX[4] = {-1.f, 1.f, 1.f, -1.f};
    const float SY[4] = {-1.f, -1.f, 1.f, 1.f};
#pragma unroll
    for (int t = 0; t < 4; t++) {
        float ux = SX[t] * haw, uy = SY[t] * hah;
        gxA[t] = acx + ac * ux - as * uy;
        gyA[t] = acy + as * ux + ac * uy;
        float vx = SX[t] * hbw, vy = SY[t] * hbh;
        gxB[t] = bcx + bc * vx - bs * vy;
        gyB[t] = bcy + bs * vx + bc * vy;
    }
#pragma unroll
    for (int t = 0; t < 4; t++) {
        float px = gxA[t] - bcx, py = gyA[t] - bcy;
        lxA[t] =  bc * px + bs * py;
        lyA[t] = -bs * px + bc * py;
        float qx = gxB[t] - acx, qy = gyB[t] - acy;
        lxB[t] =  ac * qx + as * qy;
        lyB[t] = -as * qx + ac * qy;
    }
    float cs = 0.f;
#pragma unroll
    for (int e = 0; e < 4; e++) {
        int e1 = (e + 1) & 3;
        cs += clip_contrib(gxA[e], gyA[e], gxA[e1], gyA[e1],
                           lxA[e], lyA[e], lxA[e1], lyA[e1], hbw, hbh);
    }
#pragma unroll
    for (int e = 0; e < 4; e++) {
        int e1 = (e + 1) & 3;
        cs += clip_contrib(gxB[e], gyB[e], gxB[e1], gyB[e1],
                           lxB[e], lyB[e], lxB[e1], lyB[e1], haw, hah);
    }
    float inter = 0.5f * fabsf(cs);
    float uni = aw * ah + bw * bh - inter;
    float iou = __fdividef(inter, fmaxf(uni, 1e-12f));
    return 2.f * fmaxf(iou - 0.1f, 0.f);
}

__global__ __launch_bounds__(TPB)
void fused_kernel(const float* __restrict__ pred, float* __restrict__ out,
                  int out_size)
{
    __shared__ float4 jt[WPB][4];         // j-subtile: cx, cy, rad
    __shared__ int    q[WPB][QCAP];       // warp-private active-pair queue
    __shared__ float  sr1[WPB], sr2[WPB], sr3[WPB];
    __shared__ bool   last;

    const int tid  = threadIdx.x;
    const int wid  = tid >> 5;
    const int lane = tid & 31;

    // ---- closed-form chunk decode -> (gi, gj, j-slice) ----
    int chunk = blockIdx.x * WPB + wid;   // 0..2399
    int tp = chunk >> 3, js = chunk & 7;
    const float TGP1 = 2.f * G + 1.f;     // 49
    int gi = (int)floorf((TGP1 - sqrtf(TGP1 * TGP1 - 8.f * (float)tp)) * 0.5f);
    if (gi > 0 && gi * (2 * G - gi + 1) / 2 > tp) gi--;
    if ((gi + 1) * (2 * G - gi) / 2 <= tp) gi++;
    int gj = gi + (tp - gi * (2 * G - gi + 1) / 2);

    // ---- lane's i-box (registers, float2 loads) ----
    int i = gi * 32 + lane;
    const float2* pi2 = (const float2*)(pred + i * 6);
    float2 i0 = __ldg(pi2), i1 = __ldg(pi2 + 1);
    float icx = i0.x, icy = i0.y;
    float irad = 0.5f * fast_sqrt(i1.x * i1.x + i1.y * i1.y);

    // ---- stage 4-box j-subtile (cx, cy, rad) to warp smem ----
    int jbase = gj * 32 + js * 4;
    if (lane < 4) {
        const float2* pj2 = (const float2*)(pred + (jbase + lane) * 6);
        float2 j0 = __ldg(pj2), j1 = __ldg(pj2 + 1);
        jt[wid][lane] = make_float4(j0.x, j0.y,
                                    0.5f * fast_sqrt(j1.x * j1.x + j1.y * j1.y),
                                    0.f);
    }
    __syncwarp();

    // ---- phase 1: 32 x 4 distance tests, repel, compact survivors ----
    float repel = 0.f;
    int qn = 0;
#pragma unroll
    for (int jj = 0; jj < 4; jj++) {
        float4 jb = jt[wid][jj];
        int j = jbase + jj;
        bool valid = i < j;    // gi<=gj makes this exactly "unordered pair"
        float dx = icx - jb.x, dy = icy - jb.y;
        float dist = fast_sqrt(dx * dx + dy * dy);
        if (valid) repel += 2.f * fmaxf(0.08f - dist, 0.f);
        bool act = valid && (dist < irad + jb.z);
        unsigned msk = __ballot_sync(0xFFFFFFFFu, act);
        if (act) {
            int rank = __popc(msk & ((1u << lane) - 1u));
            q[wid][qn + rank] = (i << 16) | j;
        }
        qn += __popc(msk);
    }
    __syncwarp();

    // ---- phase 2: drain queue at full lane utilization ----
    float iouv = 0.f;
    for (int base = 0; base < qn; base += 32) {
        int idx = base + lane;
        if (idx < qn) {
            int e = q[wid][idx];
            iouv += iou_hinge(pred, e >> 16, e & 0xFFFF);
        }
    }

    // ---- deterministic warp reduce (xor tree) ----
#pragma unroll
    for (int off = 16; off > 0; off >>= 1) {
        repel += __shfl_xor_sync(0xFFFFFFFFu, repel, off);
        iouv  += __shfl_xor_sync(0xFFFFFFFFu, iouv,  off);
    }
    if (lane == 0) { sr1[wid] = repel; sr2[wid] = iouv; }
    __syncthreads();

    if (tid == 0) {
        float r = 0.f, v = 0.f;
#pragma unroll
        for (int w = 0; w < WPB; w++) { r += sr1[w]; v += sr2[w]; }
        g_partial[blockIdx.x][0] = r;
        g_partial[blockIdx.x][1] = v;
        __threadfence();
        int c = atomicAdd(&g_count, 1);
        last = (c == NBLK - 1);
    }
    __syncthreads();

    // ---- last-arriving block: fixed-order final combine + size loss ----
    // (warp shfl tree + WPB loop: safe for non-power-of-2 TPB)
    if (last) {
        float r = 0.f, v = 0.f;
        for (int b = tid; b < NBLK; b += TPB) {
            r += g_partial[b][0];
            v += g_partial[b][1];
        }
        float pen = 0.f;
        for (int bi = tid; bi < M; bi += TPB) {
            const float2* pw = (const float2*)(pred + bi * 6);
            float2 wh = __ldg(pw + 1);
            pen += fmaxf(0.02f - wh.x, 0.f) + fmaxf(0.02f - wh.y, 0.f);
        }
#pragma unroll
        for (int off = 16; off > 0; off >>= 1) {
            r   += __shfl_xor_sync(0xFFFFFFFFu, r,   off);
            v   += __shfl_xor_sync(0xFFFFFFFFu, v,   off);
            pen += __shfl_xor_sync(0xFFFFFFFFu, pen, off);
        }
        if (lane == 0) { sr1[wid] = r; sr2[wid] = v; sr3[wid] = pen; }
        __syncthreads();
        if (tid == 0) {
            float fr = 0.f, fv = 0.f, fp = 0.f;
#pragma unroll
            for (int w = 0; w < WPB; w++) {
                fr += sr1[w]; fv += sr2[w]; fp += sr3[w];
            }
            float totalv = fr / (float)(M * (M - 1))
                         + fp / (float)M
                         + fv / (float)(M * M);
            for (int o = 0; o < out_size; o++) out[o] = totalv;
            g_count = 0;   // re-arm for next graph replay
        }
    }
}

extern "C" void kernel_launch(void* const* d_in, const int* in_sizes, int n_in,
                              void* d_out, int out_size) {
    const float* pred = (const float*)d_in[0];
    float* out = (float*)d_out;
    fused_kernel<<<NBLK, TPB>>>(pred, out, out_size);
}

// round 17
// speedup vs baseline: 1.0663x; 1.0663x over previous
#include <cuda_runtime.h>
#include <math.h>

#define M      768
#define G      24             // groups of 32 boxes
#define NTP    300            // G*(G+1)/2 unordered group-pairs
#define JSPLIT 8              // j-slices of 4 boxes
#define NCHUNK (NTP * JSPLIT) // 2400 chunks = 2400 warps
#define WPB    20
#define TPB    (WPB * 32)     // 640
#define NBLK   (NCHUNK / WPB) // 120 blocks -> exactly one wave
#define QCAP   128            // worst case 4 j-iters * 32 lanes
#define GW     4              // warps per merge-group
#define NGRP   (WPB / GW)     // 5 groups per block
#define GQCAP  (GW * QCAP)    // 512

__device__ float g_partial[NBLK][2];
__device__ int   g_count;     // zero-init; re-armed by finalize

// sqrt(d2) via MUFU rsqrt.approx (short chain, ~1e-7 rel err)
__device__ __forceinline__ float fast_sqrt(float d2)
{
    float r;
    asm("rsqrt.approx.f32 %0, %1;" : "=f"(r) : "f"(fmaxf(d2, 1e-30f)));
    return d2 * r;
}

// Clip directed edge (global g0->g1; same edge in clipping box's local frame
// l0->l1) against |x|<=hw,|y|<=hh. Returns cross(pa,pb) of surviving segment
// in the GLOBAL frame; 0 if edge misses box.
__device__ __forceinline__ float clip_contrib(
    float g0x, float g0y, float g1x, float g1y,
    float l0x, float l0y, float l1x, float l1y,
    float hw, float hh)
{
    float tlo = 0.f, thi = 1.f;
    bool empty = false;
#define CLIP_PLANE(D0, D1)                              \
    {                                                   \
        float d0 = (D0), d1 = (D1);                     \
        bool o0 = d0 < 0.f, o1 = d1 < 0.f;              \
        empty = empty || (o0 && o1);                    \
        float t = __fdividef(d0, d0 - d1);              \
        if (o0) tlo = fmaxf(tlo, t);                    \
        if (o1) thi = fminf(thi, t);                    \
    }
    CLIP_PLANE(hw - l0x, hw - l1x)
    CLIP_PLANE(hw + l0x, hw + l1x)
    CLIP_PLANE(hh - l0y, hh - l1y)
    CLIP_PLANE(hh + l0y, hh + l1y)
#undef CLIP_PLANE
    if (empty || tlo >= thi) return 0.f;
    float ex = g1x - g0x, ey = g1y - g0y;
    float ax = g0x + tlo * ex, ay = g0y + tlo * ey;
    float bx = g0x + thi * ex, by = g0y + thi * ey;
    return ax * by - ay * bx;
}

// Exact rotated-rect IoU hinge for pair (i,j); vectorized float2 loads.
__device__ __forceinline__ float iou_hinge(const float* __restrict__ pred,
                                           int i, int j)
{
    const float2* pa = (const float2*)(pred + i * 6);   // 8B-aligned (24B rows)
    const float2* pb = (const float2*)(pred + j * 6);
    float2 a0 = __ldg(pa), a1 = __ldg(pa + 1), a2 = __ldg(pa + 2);
    float2 b0 = __ldg(pb), b1 = __ldg(pb + 1), b2 = __ldg(pb + 2);
    float acx = a0.x, acy = a0.y, aw = a1.x, ah = a1.y, ac = a2.x, as = a2.y;
    float bcx = b0.x, bcy = b0.y, bw = b1.x, bh = b1.y, bc = b2.x, bs = b2.y;

    float haw = 0.5f * aw, hah = 0.5f * ah;
    float hbw = 0.5f * bw, hbh = 0.5f * bh;

    float gxA[4], gyA[4], gxB[4], gyB[4];
    float lxA[4], lyA[4], lxB[4], lyB[4];
    const float SX[4] = {-1.f, 1.f, 1.f, -1.f};
    const float SY[4] = {-1.f, -1.f, 1.f, 1.f};
#pragma unroll
    for (int t = 0; t < 4; t++) {
        float ux = SX[t] * haw, uy = SY[t] * hah;
        gxA[t] = acx + ac * ux - as * uy;
        gyA[t] = acy + as * ux + ac * uy;
        float vx = SX[t] * hbw, vy = SY[t] * hbh;
        gxB[t] = bcx + bc * vx - bs * vy;
        gyB[t] = bcy + bs * vx + bc * vy;
    }
#pragma unroll
    for (int t = 0; t < 4; t++) {
        float px = gxA[t] - bcx, py = gyA[t] - bcy;
        lxA[t] =  bc * px + bs * py;
        lyA[t] = -bs * px + bc * py;
        float qx = gxB[t] - acx, qy = gyB[t] - acy;
        lxB[t] =  ac * qx + as * qy;
        lyB[t] = -as * qx + ac * qy;
    }
    float cs = 0.f;
#pragma unroll
    for (int e = 0; e < 4; e++) {
        int e1 = (e + 1) & 3;
        cs += clip_contrib(gxA[e], gyA[e], gxA[e1], gyA[e1],
                           lxA[e], lyA[e], lxA[e1], lyA[e1], hbw, hbh);
    }
#pragma unroll
    for (int e = 0; e < 4; e++) {
        int e1 = (e + 1) & 3;
        cs += clip_contrib(gxB[e], gyB[e], gxB[e1], gyB[e1],
                           lxB[e], lyB[e], lxB[e1], lyB[e1], haw, hah);
    }
    float inter = 0.5f * fabsf(cs);
    float uni = aw * ah + bw * bh - inter;
    float iou = __fdividef(inter, fmaxf(uni, 1e-12f));
    return 2.f * fmaxf(iou - 0.1f, 0.f);
}

__global__ __launch_bounds__(TPB)
void fused_kernel(const float* __restrict__ pred, float* __restrict__ out,
                  int out_size)
{
    __shared__ float4 jt[WPB][4];         // j-subtile: cx, cy, rad
    __shared__ int    q[WPB][QCAP];       // warp-private survivor lists
    __shared__ int    gq[NGRP][GQCAP];    // merged per-group queues
    __shared__ int    qc[WPB];            // per-warp survivor counts
    __shared__ float  sr1[WPB], sr2[WPB], sr3[WPB];
    __shared__ bool   last;

    const int tid  = threadIdx.x;
    const int wid  = tid >> 5;
    const int lane = tid & 31;
    const int gid  = wid / GW;            // merge-group id (0..4)
    const int gl   = (wid % GW) * 32 + lane;  // lane within group (0..127)

    // ---- closed-form chunk decode -> (gi, gj, j-slice) ----
    int chunk = blockIdx.x * WPB + wid;   // 0..2399
    int tp = chunk >> 3, js = chunk & 7;
    const float TGP1 = 2.f * G + 1.f;     // 49
    int gi = (int)floorf((TGP1 - sqrtf(TGP1 * TGP1 - 8.f * (float)tp)) * 0.5f);
    if (gi > 0 && gi * (2 * G - gi + 1) / 2 > tp) gi--;
    if ((gi + 1) * (2 * G - gi) / 2 <= tp) gi++;
    int gj = gi + (tp - gi * (2 * G - gi + 1) / 2);

    // ---- lane's i-box (registers, float2 loads) ----
    int i = gi * 32 + lane;
    const float2* pi2 = (const float2*)(pred + i * 6);
    float2 i0 = __ldg(pi2), i1 = __ldg(pi2 + 1);
    float icx = i0.x, icy = i0.y;
    float irad = 0.5f * fast_sqrt(i1.x * i1.x + i1.y * i1.y);

    // ---- stage 4-box j-subtile (cx, cy, rad) to warp smem ----
    int jbase = gj * 32 + js * 4;
    if (lane < 4) {
        const float2* pj2 = (const float2*)(pred + (jbase + lane) * 6);
        float2 j0 = __ldg(pj2), j1 = __ldg(pj2 + 1);
        jt[wid][lane] = make_float4(j0.x, j0.y,
                                    0.5f * fast_sqrt(j1.x * j1.x + j1.y * j1.y),
                                    0.f);
    }
    __syncwarp();

    // ---- phase 1: 32 x 4 distance tests, repel, compact survivors ----
    float repel = 0.f;
    int qn = 0;
#pragma unroll
    for (int jj = 0; jj < 4; jj++) {
        float4 jb = jt[wid][jj];
        int j = jbase + jj;
        bool valid = i < j;    // gi<=gj makes this exactly "unordered pair"
        float dx = icx - jb.x, dy = icy - jb.y;
        float dist = fast_sqrt(dx * dx + dy * dy);
        if (valid) repel += 2.f * fmaxf(0.08f - dist, 0.f);
        bool act = valid && (dist < irad + jb.z);
        unsigned msk = __ballot_sync(0xFFFFFFFFu, act);
        if (act) {
            int rank = __popc(msk & ((1u << lane) - 1u));
            q[wid][qn + rank] = (i << 16) | j;
        }
        qn += __popc(msk);
    }
    if (lane == 0) qc[wid] = qn;

    // ---- merge the 4 warps' queues (named barrier: only this group syncs) ----
    asm volatile("bar.sync %0, %1;" :: "r"(gid + 1), "r"(GW * 32) : "memory");
    int goff = 0, gtot = 0;
#pragma unroll
    for (int w = 0; w < GW; w++) {
        int c = qc[gid * GW + w];
        if (w < (wid % GW)) goff += c;
        gtot += c;
    }
    for (int s = lane; s < qn; s += 32) gq[gid][goff + s] = q[wid][s];
    asm volatile("bar.sync %0, %1;" :: "r"(gid + 1), "r"(GW * 32) : "memory");

    // ---- phase 2: drain merged queue (typically ONE clip batch per group) ----
    float iouv = 0.f;
    for (int idx = gl; idx < gtot; idx += GW * 32) {
        int e = gq[gid][idx];
        iouv += iou_hinge(pred, e >> 16, e & 0xFFFF);
    }

    // ---- deterministic warp reduce (xor tree) ----
#pragma unroll
    for (int off = 16; off > 0; off >>= 1) {
        repel += __shfl_xor_sync(0xFFFFFFFFu, repel, off);
        iouv  += __shfl_xor_sync(0xFFFFFFFFu, iouv,  off);
    }
    if (lane == 0) { sr1[wid] = repel; sr2[wid] = iouv; }
    __syncthreads();

    if (tid == 0) {
        float r = 0.f, v = 0.f;
#pragma unroll
        for (int w = 0; w < WPB; w++) { r += sr1[w]; v += sr2[w]; }
        g_partial[blockIdx.x][0] = r;
        g_partial[blockIdx.x][1] = v;
        __threadfence();
        int c = atomicAdd(&g_count, 1);
        last = (c == NBLK - 1);
    }
    __syncthreads();

    // ---- last-arriving block: fixed-order final combine + size loss ----
    // (warp shfl tree + WPB loop: safe for non-power-of-2 TPB)
    if (last) {
        float r = 0.f, v = 0.f;
        for (int b = tid; b < NBLK; b += TPB) {
            r += g_partial[b][0];
            v += g_partial[b][1];
        }
        float pen = 0.f;
        for (int bi = tid; bi < M; bi += TPB) {
            const float2* pw = (const float2*)(pred + bi * 6);
            float2 wh = __ldg(pw + 1);
            pen += fmaxf(0.02f - wh.x, 0.f) + fmaxf(0.02f - wh.y, 0.f);
        }
#pragma unroll
        for (int off = 16; off > 0; off >>= 1) {
            r   += __shfl_xor_sync(0xFFFFFFFFu, r,   off);
            v   += __shfl_xor_sync(0xFFFFFFFFu, v,   off);
            pen += __shfl_xor_sync(0xFFFFFFFFu, pen, off);
        }
        if (lane == 0) { sr1[wid] = r; sr2[wid] = v; sr3[wid] = pen; }
        __syncthreads();
        if (tid == 0) {
            float fr = 0.f, fv = 0.f, fp = 0.f;
#pragma unroll
            for (int w = 0; w < WPB; w++) {
                fr += sr1[w]; fv += sr2[w]; fp += sr3[w];
            }
            float totalv = fr / (float)(M * (M - 1))
                         + fp / (float)M
                         + fv / (float)(M * M);
            for (int o = 0; o < out_size; o++) out[o] = totalv;
            g_count = 0;   // re-arm for next graph replay
        }
    }
}

extern "C" void kernel_launch(void* const* d_in, const int* in_sizes, int n_in,
                              void* d_out, int out_size) {
    const float* pred = (const float*)d_in[0];
    float* out = (float*)d_out;
    fused_kernel<<<NBLK, TPB>>>(pred, out, out_size);
}